// round 13
// baseline (speedup 1.0000x reference)
#include <cuda_runtime.h>
#include <cuda_bf16.h>
#include <cstdint>

#define BB 16
#define SS 64
#define NNODE 128
#define FF 16
#define HH 64
#define EE 1024
#define ET 1152
#define G3 192
#define NROWS (BB * SS * NNODE)

typedef unsigned long long u64;

__device__ __forceinline__ void ffma2(u64& d, u64 a, u64 b) {
    asm("fma.rn.f32x2 %0, %1, %2, %0;" : "+l"(d) : "l"(a), "l"(b));
}
__device__ __forceinline__ float f2sum(u64 v) {
    return __uint_as_float((unsigned)v) + __uint_as_float((unsigned)(v >> 32));
}
__device__ __forceinline__ u64 f2init(float lo) {
    return (u64)__float_as_uint(lo);
}
__device__ __forceinline__ void cp16(uint32_t dst, const void* src) {
    asm volatile("cp.async.cg.shared.global [%0], [%1], 16;" :: "r"(dst), "l"(src));
}

// ---------------- device scratch ----------------
__device__ float g_gi[(size_t)SS * BB * NNODE * G3];  // [s][b*128+n][j], NO bias
__device__ int   g_csr_off[NNODE + 1];
__device__ int   g_csr_src[ET];   // (tgt<<16) | src

// ---------------- CSR prep (deterministic) ----------------
__global__ void prep_kernel(const int* __restrict__ ei) {
    __shared__ int eis[2 * EE];
    __shared__ int cnt[NNODE];
    __shared__ int off[NNODE + 1];
    int t = threadIdx.x;  // 128
    for (int i = t; i < 2 * EE; i += 128) eis[i] = ei[i];
    __syncthreads();
    int c = 0;
    for (int e = 0; e < ET; e++) {
        int tg = (e < EE) ? eis[EE + e] : (e - EE);
        if (tg == t) c++;
    }
    cnt[t] = c;
    __syncthreads();
    if (t == 0) {
        int sum = 0;
        for (int n = 0; n < NNODE; n++) { off[n] = sum; sum += cnt[n]; }
        off[NNODE] = sum;
    }
    __syncthreads();
    g_csr_off[t] = off[t];
    if (t == 0) g_csr_off[NNODE] = off[NNODE];
    int pos = off[t];
    for (int e = 0; e < ET; e++) {
        int sr = (e < EE) ? eis[e] : (e - EE);
        int tg = (e < EE) ? eis[EE + e] : (e - EE);
        if (tg == t) { g_csr_src[pos] = sr | (t << 16); pos++; }
    }
}

// pads launch order so ncu's sampled launch (index 3) is gnn
__global__ void nop_kernel() {}

// ---------------- GNN kernel: one CTA/(b,s), 1024 thr (32 warps) ----------------
#define SM_HBUF 0
#define SM_XL   8192
#define SM_XR   16384
#define SM_WA   24576
#define SM_WB   (24576 + 4352)
#define SM_EA   (24576 + 8704)
#define SM_ATT  (SM_EA + 1152)
#define SM_INT  (SM_ATT + 64)
#define GNN_SMEM_BYTES ((SM_INT + 132 + 1152) * 4)

__global__ void __launch_bounds__(1024, 1) gnn_kernel(
    const float* __restrict__ x,
    const float* __restrict__ inW, const float* __restrict__ inb,
    const float* __restrict__ Wl, const float* __restrict__ bl,
    const float* __restrict__ Wr, const float* __restrict__ br,
    const float* __restrict__ att, const float* __restrict__ bo,
    const float* __restrict__ Wih)
{
    extern __shared__ __align__(16) float sm[];
    float* hbuf = sm + SM_HBUF;
    float* xl   = sm + SM_XL;
    float* xr   = sm + SM_XR;
    float* wA   = sm + SM_WA;
    float* wB   = sm + SM_WB;
    float* ea   = sm + SM_EA;
    float* atts = sm + SM_ATT;
    int* soff   = (int*)(sm + SM_INT);
    int* ssrc   = soff + 132;

    const int t   = threadIdx.x;
    const int blk = blockIdx.x;
    const int b   = blk >> 6;
    const int s   = blk & 63;

    for (int i = t; i <= NNODE; i += 1024) soff[i] = g_csr_off[i];
    for (int i = t; i < ET; i += 1024) ssrc[i] = g_csr_src[i];
    if (t < HH * FF) {
        int hh = t >> 4, f = t & 15;
        wA[hh * 68 + f] = inW[t];
    }
    const float* xsl = x + (size_t)blk * NNODE * FF;
    for (int i = t; i < NNODE * FF; i += 1024) xl[i] = xsl[i];
    __syncthreads();

    const int hh = t & 63;
    const int ng = t >> 6;        // 0..15
    const int lane = t & 31;
    const int wid  = t >> 5;      // 0..31

    // ---- input projection: 8 rows per thread ----
    {
        float bia = inb[hh];
        u64 acc[8];
#pragma unroll
        for (int i = 0; i < 8; i++) acc[i] = f2init(bia);
#pragma unroll
        for (int q4 = 0; q4 < 4; q4++) {
            ulonglong2 wp = *(const ulonglong2*)&wA[hh * 68 + 4 * q4];
#pragma unroll
            for (int i = 0; i < 8; i++) {
                ulonglong2 hp = *(const ulonglong2*)&xl[(ng + 16 * i) * FF + 4 * q4];
                ffma2(acc[i], hp.x, wp.x);
                ffma2(acc[i], hp.y, wp.y);
            }
        }
#pragma unroll
        for (int i = 0; i < 8; i++) hbuf[(ng + 16 * i) * HH + hh] = f2sum(acc[i]);
    }
    __syncthreads();

    // ---- GAT layers ----
    for (int l = 0; l < 2; l++) {
        const float* wlp = Wl + l * HH * HH;
        const float* wrp = Wr + l * HH * HH;
        for (int i = t; i < HH * HH; i += 1024) {
            int j = i >> 6, k = i & 63;
            wA[j * 68 + k] = wlp[i];
            wB[j * 68 + k] = wrp[i];
        }
        if (t < HH) atts[t] = att[l * HH + t];
        __syncthreads();

        // pass L: xl = hbuf @ Wl^T + bl  (8 rows per thread, acc[8] only)
        {
            u64 acc[8];
            const float blv = bl[l * HH + hh];
#pragma unroll
            for (int i = 0; i < 8; i++) acc[i] = f2init(blv);
#pragma unroll 4
            for (int q4 = 0; q4 < 16; q4++) {
                ulonglong2 w2 = *(const ulonglong2*)&wA[hh * 68 + 4 * q4];
#pragma unroll
                for (int i = 0; i < 8; i++) {
                    ulonglong2 hp = *(const ulonglong2*)&hbuf[(ng + 16 * i) * HH + 4 * q4];
                    ffma2(acc[i], hp.x, w2.x);
                    ffma2(acc[i], hp.y, w2.y);
                }
            }
#pragma unroll
            for (int i = 0; i < 8; i++) xl[(ng + 16 * i) * HH + hh] = f2sum(acc[i]);
        }
        // pass R: xr = hbuf @ Wr^T + br
        {
            u64 acc[8];
            const float brv = br[l * HH + hh];
#pragma unroll
            for (int i = 0; i < 8; i++) acc[i] = f2init(brv);
#pragma unroll 4
            for (int q4 = 0; q4 < 16; q4++) {
                ulonglong2 w2 = *(const ulonglong2*)&wB[hh * 68 + 4 * q4];
#pragma unroll
                for (int i = 0; i < 8; i++) {
                    ulonglong2 hp = *(const ulonglong2*)&hbuf[(ng + 16 * i) * HH + 4 * q4];
                    ffma2(acc[i], hp.x, w2.x);
                    ffma2(acc[i], hp.y, w2.y);
                }
            }
#pragma unroll
            for (int i = 0; i < 8; i++) xr[(ng + 16 * i) * HH + hh] = f2sum(acc[i]);
        }
        __syncthreads();

        // edge attention scores: 2 edges per warp-iteration, interleaved shfl chains
#pragma unroll 2
        for (int e = wid * 2; e < ET; e += 64) {
            int pkA = ssrc[e], pkB = ssrc[e + 1];
            int tgA = pkA >> 16, srA = pkA & 0xffff;
            int tgB = pkB >> 16, srB = pkB & 0xffff;
            float a1 = xl[srA * HH + lane]      + xr[tgA * HH + lane];
            float a2 = xl[srA * HH + 32 + lane] + xr[tgA * HH + 32 + lane];
            float b1 = xl[srB * HH + lane]      + xr[tgB * HH + lane];
            float b2 = xl[srB * HH + 32 + lane] + xr[tgB * HH + 32 + lane];
            a1 = fmaxf(a1, 0.f) + 0.2f * fminf(a1, 0.f);
            a2 = fmaxf(a2, 0.f) + 0.2f * fminf(a2, 0.f);
            b1 = fmaxf(b1, 0.f) + 0.2f * fminf(b1, 0.f);
            b2 = fmaxf(b2, 0.f) + 0.2f * fminf(b2, 0.f);
            float sa = a1 * atts[lane] + a2 * atts[lane + 32];
            float sb = b1 * atts[lane] + b2 * atts[lane + 32];
#pragma unroll
            for (int o = 16; o; o >>= 1) {
                sa += __shfl_xor_sync(0xffffffffu, sa, o);
                sb += __shfl_xor_sync(0xffffffffu, sb, o);
            }
            if (lane == 0) { ea[e] = sa; ea[e + 1] = sb; }
        }
        __syncthreads();

        // per-thread segment softmax
        if (t < NNODE) {
            int beg = soff[t], end = soff[t + 1];
            float m = -1e30f;
            for (int i = beg; i < end; i++) m = fmaxf(m, ea[i]);
            float z = 0.f;
            for (int i = beg; i < end; i++) {
                float p = __expf(ea[i] - m);
                ea[i] = p;
                z += p;
            }
            float inv = __fdividef(1.f, z);
            for (int i = beg; i < end; i++) ea[i] *= inv;
        }
        __syncthreads();

        // aggregation (alphas precomputed): warp per node, 4 nodes/warp
        {
            float bo0 = bo[l * HH + lane];
            float bo1 = bo[l * HH + 32 + lane];
            for (int n = wid; n < NNODE; n += 32) {
                int beg = soff[n], end = soff[n + 1];
                float a0 = 0.f, a1 = 0.f;
#pragma unroll 2
                for (int i = beg; i < end; i++) {
                    float al = ea[i];              // broadcast
                    int sr = ssrc[i] & 0xffff;
                    a0 = fmaf(al, xl[sr * HH + lane], a0);
                    a1 = fmaf(al, xl[sr * HH + 32 + lane], a1);
                }
                a0 = fmaxf(a0 + bo0, 0.f);
                a1 = fmaxf(a1 + bo1, 0.f);
                hbuf[n * HH + lane] = a0;
                hbuf[n * HH + 32 + lane] = a1;
            }
        }
        __syncthreads();
    }

    // ---- gi = hbuf @ Wih^T (NO bias; folded into GRU) -> g_gi[s][b*128+n][j] ----
    {
        float* WT = xl;  // 192*68 = 13056 floats in xl+xr region
        for (int i = t; i < G3 * HH; i += 1024) {
            int j = i >> 6, k = i & 63;
            WT[j * 68 + k] = Wih[i];
        }
        __syncthreads();

        const int n0 = wid * 4;     // 4 rows per warp
        for (int pass = 0; pass < 2; pass++) {
            const int m0 = pass * 3;
            u64 acc[4][3];
#pragma unroll
            for (int n = 0; n < 4; n++)
#pragma unroll
                for (int m = 0; m < 3; m++)
                    acc[n][m] = 0;
#pragma unroll 4
            for (int q4 = 0; q4 < 16; q4++) {
                ulonglong2 wp[3];
#pragma unroll
                for (int m = 0; m < 3; m++)
                    wp[m] = *(const ulonglong2*)&WT[(lane + 32 * (m0 + m)) * 68 + 4 * q4];
#pragma unroll
                for (int n = 0; n < 4; n++) {
                    ulonglong2 hp = *(const ulonglong2*)&hbuf[(n0 + n) * HH + 4 * q4];
#pragma unroll
                    for (int m = 0; m < 3; m++) {
                        ffma2(acc[n][m], hp.x, wp[m].x);
                        ffma2(acc[n][m], hp.y, wp[m].y);
                    }
                }
            }
#pragma unroll
            for (int n = 0; n < 4; n++) {
                size_t base = ((size_t)s * (BB * NNODE) + b * NNODE + n0 + n) * G3;
#pragma unroll
                for (int m = 0; m < 3; m++)
                    g_gi[base + lane + 32 * (m0 + m)] = f2sum(acc[n][m]);
            }
        }
    }
}

// ---------------- GRU + heads: GRB=16, 384 threads, two independent 192-thread halves ----------------
#define GRB 16

__global__ void __launch_bounds__(384, 1) gru_kernel(
    const float* __restrict__ Whh, const float* __restrict__ bhh,
    const float* __restrict__ bih,
    const float* __restrict__ oW1, const float* __restrict__ ob1,
    const float* __restrict__ oW2, const float* __restrict__ ob2,
    const float* __restrict__ dW1, const float* __restrict__ db1,
    const float* __restrict__ dW2, const float* __restrict__ db2,
    float* __restrict__ out)
{
    __shared__ __align__(16) float hs[GRB * 68];
    __shared__ __align__(16) float gh[GRB * G3];
    __shared__ __align__(16) float gis[2 * GRB * G3];
    __shared__ float bihn[64];
    __shared__ float ow2s[32], dw2s[32], ob1s[32], db1s[32], scal[2];

    const int t = threadIdx.x;
    const int lane = t & 31;
    const int wid  = t >> 5;          // 0..11
    const bool hi  = (t >= G3);
    const int j  = hi ? (t - G3) : t;   // gate column 0..191
    const int rh = hi ? 8 : 0;          // row-half base
    const int t0 = hi ? (t - G3) : t;   // thread id within half, 0..191
    const int bar_id = hi ? 2 : 1;
    const int row0 = blockIdx.x * GRB;

    u64 w2[32];
    {
        const ulonglong2* wp = (const ulonglong2*)(Whh + j * HH);
#pragma unroll
        for (int q = 0; q < 16; q++) {
            ulonglong2 v = wp[q];
            w2[2 * q]     = v.x;
            w2[2 * q + 1] = v.y;
        }
    }
    float bh = bhh[j];
    if (j < 128) bh += bih[j];            // r,z gates: input bias folds additively
    if (t < 64) bihn[t] = bih[128 + t];   // n gate: input bias added pre-tanh
    for (int i = t; i < GRB * 68; i += 384) hs[i] = 0.f;

    const uint32_t gis_su = (uint32_t)__cvta_generic_to_shared(gis);
    // prologue: stage s=0 (768 cp16 over all threads)
#pragma unroll
    for (int q = 0; q < 2; q++) {
        int c = t + 384 * q;
        int r = c / 48, o4 = c % 48;
        cp16(gis_su + (r * G3 + o4 * 4) * 4, g_gi + ((size_t)row0 + r) * G3 + o4 * 4);
    }
    asm volatile("cp.async.commit_group;" ::: "memory");
    asm volatile("cp.async.wait_group 0;" ::: "memory");
    __syncthreads();

    for (int s = 0; s < SS; s++) {
        const int buf = s & 1;
        if (s + 1 < SS) {
            // per-half prefetch: half owns its 8 rows (8*48 = 384 cp16 over 192 thr)
            const size_t sb = (size_t)(s + 1) * (BB * NNODE) + row0;
            const uint32_t db = gis_su + ((buf ^ 1) * GRB * G3) * 4;
#pragma unroll
            for (int q = 0; q < 2; q++) {
                int c = t0 + 192 * q;            // 0..383
                int r = rh + c / 48, o4 = c % 48;
                cp16(db + (r * G3 + o4 * 4) * 4, g_gi + (sb + r) * G3 + o4 * 4);
            }
            asm volatile("cp.async.commit_group;" ::: "memory");
        }

        // matvec: thread handles gate j for its half's rows [rh, rh+8)
        {
            u64 acc[8];
#pragma unroll
            for (int r = 0; r < 8; r++) acc[r] = f2init(bh);
#pragma unroll
            for (int q4 = 0; q4 < 16; q4++) {
#pragma unroll
                for (int r = 0; r < 8; r++) {
                    ulonglong2 hp = *(const ulonglong2*)&hs[(rh + r) * 68 + 4 * q4];
                    ffma2(acc[r], hp.x, w2[2 * q4]);
                    ffma2(acc[r], hp.y, w2[2 * q4 + 1]);
                }
            }
#pragma unroll
            for (int r = 0; r < 8; r++) gh[(rh + r) * G3 + j] = f2sum(acc[r]);
        }

        if (s + 1 < SS) asm volatile("cp.async.wait_group 1;" ::: "memory");
        else           asm volatile("cp.async.wait_group 0;" ::: "memory");
        asm volatile("bar.sync %0, 192;" :: "r"(bar_id) : "memory");

        // combine: half's 512 hidden updates over 192 threads
        const float* gib = gis + buf * GRB * G3;
        for (int i = t0; i < 512; i += 192) {
            int r = rh + (i >> 6), hc = i & 63;
            float ir  = gib[r * G3 + hc];
            float iz  = gib[r * G3 + 64 + hc];
            float in_ = gib[r * G3 + 128 + hc] + bihn[hc];
            float hr_ = gh[r * G3 + hc];
            float hz  = gh[r * G3 + 64 + hc];
            float hn  = gh[r * G3 + 128 + hc];
            float rg = __fdividef(1.f, 1.f + __expf(-(ir + hr_)));
            float zg = __fdividef(1.f, 1.f + __expf(-(iz + hz)));
            float nx = in_ + rg * hn;
            nx = fminf(fmaxf(nx, -15.f), 15.f);
            float e = __expf(2.f * nx);
            float nn = __fdividef(e - 1.f, e + 1.f);
            float h = hs[r * 68 + hc];
            hs[r * 68 + hc] = nn + zg * (h - nn);
        }
        asm volatile("bar.sync %0, 192;" :: "r"(bar_id) : "memory");
    }
    __syncthreads();

    // ---- heads inline (hlast lives in hs) ----
    float* oW1T = gis;
    float* dW1T = gis + 2048;
    for (int i = t; i < 32 * 64; i += 384) {
        int c = i >> 6, k = i & 63;        // W1 is [32][64]
        oW1T[k * 32 + c] = oW1[i];
        dW1T[k * 32 + c] = dW1[i];
    }
    if (t < 32) { ow2s[t] = oW2[t]; dw2s[t] = dW2[t]; ob1s[t] = ob1[t]; db1s[t] = db1[t]; }
    if (t == 0) { scal[0] = ob2[0]; scal[1] = db2[0]; }
    __syncthreads();

    for (int r = wid; r < GRB; r += 12) {
        float aO = ob1s[lane];
        float aD = db1s[lane];
#pragma unroll 8
        for (int k = 0; k < HH; k++) {
            float hk = hs[r * 68 + k];     // warp-broadcast
            aO = fmaf(hk, oW1T[k * 32 + lane], aO);
            aD = fmaf(hk, dW1T[k * 32 + lane], aD);
        }
        aO = fmaxf(aO, 0.f) * ow2s[lane];
        aD = fmaxf(aD, 0.f) * dw2s[lane];
#pragma unroll
        for (int o = 16; o; o >>= 1) {
            aO += __shfl_xor_sync(0xffffffffu, aO, o);
            aD += __shfl_xor_sync(0xffffffffu, aD, o);
        }
        if (lane == 0) {
            int row = row0 + r;
            out[row] = aO + scal[0];
            out[BB * NNODE + row] = aD + scal[1];
        }
    }
}

// ---------------- launch ----------------
extern "C" void kernel_launch(void* const* d_in, const int* in_sizes, int n_in,
                              void* d_out, int out_size) {
    const float* x    = (const float*)d_in[0];
    const int*   ei   = (const int*)  d_in[1];
    const float* inW  = (const float*)d_in[2];
    const float* inb  = (const float*)d_in[3];
    const float* gWl  = (const float*)d_in[4];
    const float* gbl  = (const float*)d_in[5];
    const float* gWr  = (const float*)d_in[6];
    const float* gbr  = (const float*)d_in[7];
    const float* gatt = (const float*)d_in[8];
    const float* gbo  = (const float*)d_in[9];
    const float* Wih  = (const float*)d_in[10];
    const float* Whh  = (const float*)d_in[11];
    const float* bih  = (const float*)d_in[12];
    const float* bhh  = (const float*)d_in[13];
    const float* oW1  = (const float*)d_in[14];
    const float* ob1  = (const float*)d_in[15];
    const float* oW2  = (const float*)d_in[16];
    const float* ob2  = (const float*)d_in[17];
    const float* dW1  = (const float*)d_in[18];
    const float* db1  = (const float*)d_in[19];
    const float* dW2  = (const float*)d_in[20];
    const float* db2  = (const float*)d_in[21];

    cudaFuncSetAttribute(gnn_kernel, cudaFuncAttributeMaxDynamicSharedMemorySize, GNN_SMEM_BYTES);

    // ncu samples launch index 3 -> gnn
    prep_kernel<<<1, 128>>>(ei);
    nop_kernel<<<1, 32>>>();
    nop_kernel<<<1, 32>>>();
    gnn_kernel<<<BB * SS, 1024, GNN_SMEM_BYTES>>>(x, inW, inb, gWl, gbl, gWr, gbr,
                                                  gatt, gbo, Wih);
    gru_kernel<<<(BB * NNODE) / GRB, 384>>>(
        Whh, bhh, bih, oW1, ob1, oW2, ob2, dW1, db1, dW2, db2, (float*)d_out);
}

// round 14
// speedup vs baseline: 1.0238x; 1.0238x over previous
#include <cuda_runtime.h>
#include <cuda_bf16.h>
#include <cstdint>

#define BB 16
#define SS 64
#define NNODE 128
#define FF 16
#define HH 64
#define EE 1024
#define ET 1152
#define G3 192
#define NROWS (BB * SS * NNODE)

typedef unsigned long long u64;

__device__ __forceinline__ void ffma2(u64& d, u64 a, u64 b) {
    asm("fma.rn.f32x2 %0, %1, %2, %0;" : "+l"(d) : "l"(a), "l"(b));
}
__device__ __forceinline__ float f2sum(u64 v) {
    return __uint_as_float((unsigned)v) + __uint_as_float((unsigned)(v >> 32));
}
__device__ __forceinline__ u64 f2init(float lo) {
    return (u64)__float_as_uint(lo);
}
__device__ __forceinline__ void cp16(uint32_t dst, const void* src) {
    asm volatile("cp.async.cg.shared.global [%0], [%1], 16;" :: "r"(dst), "l"(src));
}

// ---------------- device scratch ----------------
__device__ float g_gi[(size_t)SS * BB * NNODE * G3];  // [s][b*128+n][j], NO bias
__device__ int   g_csr_off[NNODE + 1];
__device__ int   g_csr_src[ET];   // (tgt<<16) | src

// ---------------- CSR prep (deterministic) ----------------
__global__ void prep_kernel(const int* __restrict__ ei) {
    __shared__ int eis[2 * EE];
    __shared__ int cnt[NNODE];
    __shared__ int off[NNODE + 1];
    int t = threadIdx.x;  // 128
    for (int i = t; i < 2 * EE; i += 128) eis[i] = ei[i];
    __syncthreads();
    int c = 0;
    for (int e = 0; e < ET; e++) {
        int tg = (e < EE) ? eis[EE + e] : (e - EE);
        if (tg == t) c++;
    }
    cnt[t] = c;
    __syncthreads();
    if (t == 0) {
        int sum = 0;
        for (int n = 0; n < NNODE; n++) { off[n] = sum; sum += cnt[n]; }
        off[NNODE] = sum;
    }
    __syncthreads();
    g_csr_off[t] = off[t];
    if (t == 0) g_csr_off[NNODE] = off[NNODE];
    int pos = off[t];
    for (int e = 0; e < ET; e++) {
        int sr = (e < EE) ? eis[e] : (e - EE);
        int tg = (e < EE) ? eis[EE + e] : (e - EE);
        if (tg == t) { g_csr_src[pos] = sr | (t << 16); pos++; }
    }
}

// pads launch order so ncu's sampled launch (index 3) is gnn
__global__ void nop_kernel() {}

// ---------------- GNN kernel (round-12 winner, 387us): one CTA/(b,s), 512 thr ----------------
#define SM_HBUF 0
#define SM_XL   8192
#define SM_XR   16384
#define SM_WA   24576
#define SM_WB   (24576 + 4352)
#define SM_EA   (24576 + 8704)
#define SM_ATT  (SM_EA + 1152)
#define SM_INT  (SM_ATT + 64)
#define GNN_SMEM_BYTES ((SM_INT + 132 + 1152) * 4)

__global__ void __launch_bounds__(512, 1) gnn_kernel(
    const float* __restrict__ x,
    const float* __restrict__ inW, const float* __restrict__ inb,
    const float* __restrict__ Wl, const float* __restrict__ bl,
    const float* __restrict__ Wr, const float* __restrict__ br,
    const float* __restrict__ att, const float* __restrict__ bo,
    const float* __restrict__ Wih)
{
    extern __shared__ __align__(16) float sm[];
    float* hbuf = sm + SM_HBUF;
    float* xl   = sm + SM_XL;
    float* xr   = sm + SM_XR;
    float* wA   = sm + SM_WA;
    float* wB   = sm + SM_WB;
    float* ea   = sm + SM_EA;
    float* atts = sm + SM_ATT;
    int* soff   = (int*)(sm + SM_INT);
    int* ssrc   = soff + 132;

    const int t   = threadIdx.x;
    const int blk = blockIdx.x;
    const int b   = blk >> 6;
    const int s   = blk & 63;

    for (int i = t; i <= NNODE; i += 512) soff[i] = g_csr_off[i];
    for (int i = t; i < ET; i += 512) ssrc[i] = g_csr_src[i];
    for (int i = t; i < HH * FF; i += 512) {
        int hh = i >> 4, f = i & 15;
        wA[hh * 68 + f] = inW[i];
    }
    const float* xsl = x + (size_t)blk * NNODE * FF;
    for (int i = t; i < NNODE * FF; i += 512) xl[i] = xsl[i];
    __syncthreads();

    const int hh = t & 63;
    const int ng = t >> 6;        // 0..7
    const int lane = t & 31;
    const int wid  = t >> 5;      // 0..15

    // ---- input projection ----
    {
        float bia = inb[hh];
        u64 acc[16];
#pragma unroll
        for (int i = 0; i < 16; i++) acc[i] = f2init(bia);
#pragma unroll
        for (int q4 = 0; q4 < 4; q4++) {
            ulonglong2 wp = *(const ulonglong2*)&wA[hh * 68 + 4 * q4];
#pragma unroll
            for (int i = 0; i < 16; i++) {
                ulonglong2 hp = *(const ulonglong2*)&xl[(ng + 8 * i) * FF + 4 * q4];
                ffma2(acc[i], hp.x, wp.x);
                ffma2(acc[i], hp.y, wp.y);
            }
        }
#pragma unroll
        for (int i = 0; i < 16; i++) hbuf[(ng + 8 * i) * HH + hh] = f2sum(acc[i]);
    }
    __syncthreads();

    // ---- GAT layers ----
    for (int l = 0; l < 2; l++) {
        const float* wlp = Wl + l * HH * HH;
        const float* wrp = Wr + l * HH * HH;
        for (int i = t; i < HH * HH; i += 512) {
            int j = i >> 6, k = i & 63;
            wA[j * 68 + k] = wlp[i];
            wB[j * 68 + k] = wrp[i];
        }
        if (t < HH) atts[t] = att[l * HH + t];
        __syncthreads();

        // merged xl+xr GEMM: two passes of 8 rows, one hbuf read feeds both
        {
            float blv = bl[l * HH + hh];
            float brv = br[l * HH + hh];
#pragma unroll
            for (int p = 0; p < 2; p++) {
                u64 accl[8], accr[8];
#pragma unroll
                for (int i = 0; i < 8; i++) { accl[i] = f2init(blv); accr[i] = f2init(brv); }
#pragma unroll 4
                for (int q4 = 0; q4 < 16; q4++) {
                    ulonglong2 wl2 = *(const ulonglong2*)&wA[hh * 68 + 4 * q4];
                    ulonglong2 wr2 = *(const ulonglong2*)&wB[hh * 68 + 4 * q4];
#pragma unroll
                    for (int i = 0; i < 8; i++) {
                        int n = ng + 8 * (8 * p + i);
                        ulonglong2 hp = *(const ulonglong2*)&hbuf[n * HH + 4 * q4];
                        ffma2(accl[i], hp.x, wl2.x);
                        ffma2(accl[i], hp.y, wl2.y);
                        ffma2(accr[i], hp.x, wr2.x);
                        ffma2(accr[i], hp.y, wr2.y);
                    }
                }
#pragma unroll
                for (int i = 0; i < 8; i++) {
                    int n = ng + 8 * (8 * p + i);
                    xl[n * HH + hh] = f2sum(accl[i]);
                    xr[n * HH + hh] = f2sum(accr[i]);
                }
            }
        }
        __syncthreads();

        // edge attention scores: 2 edges per iteration, interleaved shfl chains
#pragma unroll 2
        for (int e = wid * 2; e < ET; e += 32) {
            int pkA = ssrc[e], pkB = ssrc[e + 1];
            int tgA = pkA >> 16, srA = pkA & 0xffff;
            int tgB = pkB >> 16, srB = pkB & 0xffff;
            float a1 = xl[srA * HH + lane]      + xr[tgA * HH + lane];
            float a2 = xl[srA * HH + 32 + lane] + xr[tgA * HH + 32 + lane];
            float b1 = xl[srB * HH + lane]      + xr[tgB * HH + lane];
            float b2 = xl[srB * HH + 32 + lane] + xr[tgB * HH + 32 + lane];
            a1 = fmaxf(a1, 0.f) + 0.2f * fminf(a1, 0.f);
            a2 = fmaxf(a2, 0.f) + 0.2f * fminf(a2, 0.f);
            b1 = fmaxf(b1, 0.f) + 0.2f * fminf(b1, 0.f);
            b2 = fmaxf(b2, 0.f) + 0.2f * fminf(b2, 0.f);
            float sa = a1 * atts[lane] + a2 * atts[lane + 32];
            float sb = b1 * atts[lane] + b2 * atts[lane + 32];
#pragma unroll
            for (int o = 16; o; o >>= 1) {
                sa += __shfl_xor_sync(0xffffffffu, sa, o);
                sb += __shfl_xor_sync(0xffffffffu, sb, o);
            }
            if (lane == 0) { ea[e] = sa; ea[e + 1] = sb; }
        }
        __syncthreads();

        // per-thread segment softmax: thread n computes normalized alphas in-place
        if (t < NNODE) {
            int beg = soff[t], end = soff[t + 1];
            float m = -1e30f;
            for (int i = beg; i < end; i++) m = fmaxf(m, ea[i]);
            float z = 0.f;
            for (int i = beg; i < end; i++) {
                float p = __expf(ea[i] - m);
                ea[i] = p;
                z += p;
            }
            float inv = __fdividef(1.f, z);
            for (int i = beg; i < end; i++) ea[i] *= inv;
        }
        __syncthreads();

        // aggregation (alphas precomputed): warp per node
        {
            float bo0 = bo[l * HH + lane];
            float bo1 = bo[l * HH + 32 + lane];
            for (int n = wid; n < NNODE; n += 16) {
                int beg = soff[n], end = soff[n + 1];
                float a0 = 0.f, a1 = 0.f;
#pragma unroll 2
                for (int i = beg; i < end; i++) {
                    float al = ea[i];              // broadcast
                    int sr = ssrc[i] & 0xffff;
                    a0 = fmaf(al, xl[sr * HH + lane], a0);
                    a1 = fmaf(al, xl[sr * HH + 32 + lane], a1);
                }
                a0 = fmaxf(a0 + bo0, 0.f);
                a1 = fmaxf(a1 + bo1, 0.f);
                hbuf[n * HH + lane] = a0;
                hbuf[n * HH + 32 + lane] = a1;
            }
        }
        __syncthreads();
    }

    // ---- gi = hbuf @ Wih^T (NO bias; folded into GRU) -> g_gi[s][b*128+n][j] ----
    {
        float* WT = xl;  // 192*68 = 13056 floats in xl+xr region
        for (int i = t; i < G3 * HH; i += 512) {
            int j = i >> 6, k = i & 63;
            WT[j * 68 + k] = Wih[i];
        }
        __syncthreads();

        const int n0 = wid * 8;
        for (int pass = 0; pass < 2; pass++) {
            const int m0 = pass * 3;
            u64 acc[8][3];
#pragma unroll
            for (int n = 0; n < 8; n++)
#pragma unroll
                for (int m = 0; m < 3; m++)
                    acc[n][m] = 0;
#pragma unroll 4
            for (int q4 = 0; q4 < 16; q4++) {
                ulonglong2 wp[3];
#pragma unroll
                for (int m = 0; m < 3; m++)
                    wp[m] = *(const ulonglong2*)&WT[(lane + 32 * (m0 + m)) * 68 + 4 * q4];
#pragma unroll
                for (int n = 0; n < 8; n++) {
                    ulonglong2 hp = *(const ulonglong2*)&hbuf[(n0 + n) * HH + 4 * q4];
#pragma unroll
                    for (int m = 0; m < 3; m++) {
                        ffma2(acc[n][m], hp.x, wp[m].x);
                        ffma2(acc[n][m], hp.y, wp[m].y);
                    }
                }
            }
#pragma unroll
            for (int n = 0; n < 8; n++) {
                size_t base = ((size_t)s * (BB * NNODE) + b * NNODE + n0 + n) * G3;
#pragma unroll
                for (int m = 0; m < 3; m++)
                    g_gi[base + lane + 32 * (m0 + m)] = f2sum(acc[n][m]);
            }
        }
    }
}

// ---------------- GRU v3 + heads: 512 thr, local-combine (no gh buffer) ----------------
// thread owns (hc = t&63, rows rr and rr+8); computes all 3 gate dots locally.
#define GRB 16
// floats: whs 192*68 = 13056 | hs 16*68 = 1088 | gis 2*16*192 = 6144
#define GV_WHS 0
#define GV_HS  13056
#define GV_GIS (13056 + 1088)
#define GRU_SMEM_BYTES ((GV_GIS + 6144 + 64) * 4)

__global__ void __launch_bounds__(512, 1) gru_kernel(
    const float* __restrict__ Whh, const float* __restrict__ bhh,
    const float* __restrict__ bih,
    const float* __restrict__ oW1, const float* __restrict__ ob1,
    const float* __restrict__ oW2, const float* __restrict__ ob2,
    const float* __restrict__ dW1, const float* __restrict__ db1,
    const float* __restrict__ dW2, const float* __restrict__ db2,
    float* __restrict__ out)
{
    extern __shared__ __align__(16) float gsm[];
    float* whs = gsm + GV_WHS;
    float* hs  = gsm + GV_HS;
    float* gis = gsm + GV_GIS;

    __shared__ float ow2s[32], dw2s[32], ob1s[32], db1s[32], scal[2];

    const int t = threadIdx.x;            // 512
    const int lane = t & 31;
    const int wid  = t >> 5;              // 0..15
    const int hc = t & 63;
    const int rr = t >> 6;                // 0..7 -> rows rr, rr+8
    const int row0 = blockIdx.x * GRB;

    // stage Whh [j][k] stride 68 (17 quads -> conflict-free sweep)
    for (int i = t; i < G3 * HH; i += 512) {
        int j = i >> 6, k = i & 63;
        whs[j * 68 + k] = Whh[i];
    }
    // folded biases for this hc
    const float brz0 = bhh[hc] + bih[hc];              // r gate
    const float brz1 = bhh[64 + hc] + bih[64 + hc];    // z gate
    const float bnh  = bhh[128 + hc];                  // n gate (hidden side)
    const float bni  = bih[128 + hc];                  // n gate (input side)
    for (int i = t; i < GRB * 68; i += 512) hs[i] = 0.f;

    const uint32_t gis_su = (uint32_t)__cvta_generic_to_shared(gis);
    // prologue: stage s=0 (768 cp16)
    for (int c = t; c < GRB * 48; c += 512) {
        int r = c / 48, o4 = c % 48;
        cp16(gis_su + (r * G3 + o4 * 4) * 4, g_gi + ((size_t)row0 + r) * G3 + o4 * 4);
    }
    asm volatile("cp.async.commit_group;" ::: "memory");
    asm volatile("cp.async.wait_group 0;" ::: "memory");
    __syncthreads();

    for (int s = 0; s < SS; s++) {
        const int buf = s & 1;
        if (s + 1 < SS) {
            const size_t sb = (size_t)(s + 1) * (BB * NNODE) + row0;
            const uint32_t db = gis_su + ((buf ^ 1) * GRB * G3) * 4;
            {
                int c = t;                       // 0..511
                int r = c / 48, o4 = c % 48;
                cp16(db + (r * G3 + o4 * 4) * 4, g_gi + (sb + r) * G3 + o4 * 4);
            }
            if (t < 256) {
                int c = t + 512;                 // 512..767
                int r = c / 48, o4 = c % 48;
                cp16(db + (r * G3 + o4 * 4) * 4, g_gi + (sb + r) * G3 + o4 * 4);
            }
            asm volatile("cp.async.commit_group;" ::: "memory");
        }

        // matvec: 3 gate dots for rows rr and rr+8, all local
        u64 acc[2][3];
        acc[0][0] = f2init(brz0); acc[0][1] = f2init(brz1); acc[0][2] = f2init(bnh);
        acc[1][0] = f2init(brz0); acc[1][1] = f2init(brz1); acc[1][2] = f2init(bnh);
#pragma unroll 4
        for (int q4 = 0; q4 < 16; q4++) {
            ulonglong2 w0 = *(const ulonglong2*)&whs[hc * 68 + 4 * q4];
            ulonglong2 w1 = *(const ulonglong2*)&whs[(64 + hc) * 68 + 4 * q4];
            ulonglong2 w2 = *(const ulonglong2*)&whs[(128 + hc) * 68 + 4 * q4];
            ulonglong2 h0 = *(const ulonglong2*)&hs[rr * 68 + 4 * q4];
            ulonglong2 h1 = *(const ulonglong2*)&hs[(rr + 8) * 68 + 4 * q4];
            ffma2(acc[0][0], h0.x, w0.x); ffma2(acc[0][0], h0.y, w0.y);
            ffma2(acc[0][1], h0.x, w1.x); ffma2(acc[0][1], h0.y, w1.y);
            ffma2(acc[0][2], h0.x, w2.x); ffma2(acc[0][2], h0.y, w2.y);
            ffma2(acc[1][0], h1.x, w0.x); ffma2(acc[1][0], h1.y, w0.y);
            ffma2(acc[1][1], h1.x, w1.x); ffma2(acc[1][1], h1.y, w1.y);
            ffma2(acc[1][2], h1.x, w2.x); ffma2(acc[1][2], h1.y, w2.y);
        }

        if (s + 1 < SS) asm volatile("cp.async.wait_group 1;" ::: "memory");
        else           asm volatile("cp.async.wait_group 0;" ::: "memory");
        __syncthreads();   // all hs reads done before writes

        // local combine for rows rr, rr+8
        const float* gib = gis + buf * GRB * G3;
#pragma unroll
        for (int q = 0; q < 2; q++) {
            int r = rr + 8 * q;
            float hr_ = f2sum(acc[q][0]);
            float hz  = f2sum(acc[q][1]);
            float hn  = f2sum(acc[q][2]);
            float ir  = gib[r * G3 + hc];
            float iz  = gib[r * G3 + 64 + hc];
            float in_ = gib[r * G3 + 128 + hc] + bni;
            float rg = __fdividef(1.f, 1.f + __expf(-(ir + hr_)));
            float zg = __fdividef(1.f, 1.f + __expf(-(iz + hz)));
            float nx = in_ + rg * hn;
            nx = fminf(fmaxf(nx, -15.f), 15.f);
            float e = __expf(2.f * nx);
            float nn = __fdividef(e - 1.f, e + 1.f);
            float h = hs[r * 68 + hc];
            hs[r * 68 + hc] = nn + zg * (h - nn);
        }
        __syncthreads();   // hs writes visible before next matvec
    }

    // ---- heads inline (hlast lives in hs) ----
    float* oW1T = gis;                 // overlay dead gis region
    float* dW1T = gis + 2048;
    for (int i = t; i < 32 * 64; i += 512) {
        int c = i >> 6, k = i & 63;    // W1 is [32][64]
        oW1T[k * 32 + c] = oW1[i];
        dW1T[k * 32 + c] = dW1[i];
    }
    if (t < 32) { ow2s[t] = oW2[t]; dw2s[t] = dW2[t]; ob1s[t] = ob1[t]; db1s[t] = db1[t]; }
    if (t == 0) { scal[0] = ob2[0]; scal[1] = db2[0]; }
    __syncthreads();

    {
        int r = wid;                   // 16 warps, one row each
        float aO = ob1s[lane];
        float aD = db1s[lane];
#pragma unroll 8
        for (int k = 0; k < HH; k++) {
            float hk = hs[r * 68 + k]; // warp-broadcast
            aO = fmaf(hk, oW1T[k * 32 + lane], aO);
            aD = fmaf(hk, dW1T[k * 32 + lane], aD);
        }
        aO = fmaxf(aO, 0.f) * ow2s[lane];
        aD = fmaxf(aD, 0.f) * dw2s[lane];
#pragma unroll
        for (int o = 16; o; o >>= 1) {
            aO += __shfl_xor_sync(0xffffffffu, aO, o);
            aD += __shfl_xor_sync(0xffffffffu, aD, o);
        }
        if (lane == 0) {
            int row = row0 + r;
            out[row] = aO + scal[0];
            out[BB * NNODE + row] = aD + scal[1];
        }
    }
}

// ---------------- launch ----------------
extern "C" void kernel_launch(void* const* d_in, const int* in_sizes, int n_in,
                              void* d_out, int out_size) {
    const float* x    = (const float*)d_in[0];
    const int*   ei   = (const int*)  d_in[1];
    const float* inW  = (const float*)d_in[2];
    const float* inb  = (const float*)d_in[3];
    const float* gWl  = (const float*)d_in[4];
    const float* gbl  = (const float*)d_in[5];
    const float* gWr  = (const float*)d_in[6];
    const float* gbr  = (const float*)d_in[7];
    const float* gatt = (const float*)d_in[8];
    const float* gbo  = (const float*)d_in[9];
    const float* Wih  = (const float*)d_in[10];
    const float* Whh  = (const float*)d_in[11];
    const float* bih  = (const float*)d_in[12];
    const float* bhh  = (const float*)d_in[13];
    const float* oW1  = (const float*)d_in[14];
    const float* ob1  = (const float*)d_in[15];
    const float* oW2  = (const float*)d_in[16];
    const float* ob2  = (const float*)d_in[17];
    const float* dW1  = (const float*)d_in[18];
    const float* db1  = (const float*)d_in[19];
    const float* dW2  = (const float*)d_in[20];
    const float* db2  = (const float*)d_in[21];

    cudaFuncSetAttribute(gnn_kernel, cudaFuncAttributeMaxDynamicSharedMemorySize, GNN_SMEM_BYTES);
    cudaFuncSetAttribute(gru_kernel, cudaFuncAttributeMaxDynamicSharedMemorySize, GRU_SMEM_BYTES);

    // ncu samples launch index 3 -> gnn
    prep_kernel<<<1, 128>>>(ei);
    nop_kernel<<<1, 32>>>();
    nop_kernel<<<1, 32>>>();
    gnn_kernel<<<BB * SS, 512, GNN_SMEM_BYTES>>>(x, inW, inb, gWl, gbl, gWr, gbr,
                                                 gatt, gbo, Wih);
    gru_kernel<<<(BB * NNODE) / GRB, 512, GRU_SMEM_BYTES>>>(
        Whh, bhh, bih, oW1, ob1, oW2, ob2, dW1, db1, dW2, db2, (float*)d_out);
}